// round 13
// baseline (speedup 1.0000x reference)
#include <cuda_runtime.h>
#include <cuda_fp16.h>
#include <cstdint>
#include <math.h>

using u32 = unsigned int;

#define B_  8
#define S_  2048
#define D_  64
#define H_  8
#define HD_ 512
#define BS_ (B_ * S_)       // 16384 rows
#define GH_ (B_ * H_)       // 64 "batch-heads" in the flat view
#define NTOT_ (BS_ * HD_)   // 8388608 elements per QKV buffer

// Scratch (device globals — no allocation allowed in kernel_launch)
__device__ __half g_qh[NTOT_];        // Q pre-scaled by log2(e)/8
__device__ __half g_kh[NTOT_];
__device__ __half g_vh[NTOT_];
__device__ __half g_wot[64 * 512];    // Wo transposed [n][k], fp16

#define ONES_H2 0x3C003C00u     // half2(1.0, 1.0)

// ---------------------------------------------------------------------------
// helpers
// ---------------------------------------------------------------------------
__device__ __forceinline__ u32 pack_h2(float a, float b) {
    __half2 h = __floats2half2_rn(a, b);
    return *(u32*)&h;
}

__device__ __forceinline__ u32 ex2_h2(float a, float b) {
    __half2 h = __floats2half2_rn(a, b);
    u32 x = *(u32*)&h, y;
    asm("ex2.approx.f16x2 %0, %1;" : "=r"(y) : "r"(x));
    return y;
}

__device__ __forceinline__ u32 s2u(const void* p) {
    return (u32)__cvta_generic_to_shared(p);
}

__device__ __forceinline__ void ldsm4(u32 r[4], u32 addr) {
    asm volatile("ldmatrix.sync.aligned.m8n8.x4.shared.b16 {%0,%1,%2,%3}, [%4];"
                 : "=r"(r[0]), "=r"(r[1]), "=r"(r[2]), "=r"(r[3]) : "r"(addr));
}

__device__ __forceinline__ void ldsm4t(u32 r[4], u32 addr) {
    asm volatile("ldmatrix.sync.aligned.m8n8.x4.trans.shared.b16 {%0,%1,%2,%3}, [%4];"
                 : "=r"(r[0]), "=r"(r[1]), "=r"(r[2]), "=r"(r[3]) : "r"(addr));
}

__device__ __forceinline__ void mma_f16(float c[4], const u32 a[4],
                                        const u32 b0, const u32 b1) {
    asm volatile(
        "mma.sync.aligned.m16n8k16.row.col.f32.f16.f16.f32 "
        "{%0,%1,%2,%3}, {%4,%5,%6,%7}, {%8,%9}, {%0,%1,%2,%3};"
        : "+f"(c[0]), "+f"(c[1]), "+f"(c[2]), "+f"(c[3])
        : "r"(a[0]), "r"(a[1]), "r"(a[2]), "r"(a[3]), "r"(b0), "r"(b1));
}

// ---------------------------------------------------------------------------
// Kernel 0: Wo -> fp16 transposed [n][k] (smem transpose, coalesced both ways)
// ---------------------------------------------------------------------------
__global__ void wo_prep(const float* __restrict__ Wo)
{
    __shared__ __half t[64][72];
    const int k0 = blockIdx.x * 64;
    const int tid = threadIdx.x;
    for (int i = tid; i < 4096; i += 256) {
        int k = i >> 6, n = i & 63;                 // read coalesced over n
        t[n][k] = __float2half(Wo[(k0 + k) * D_ + n]);
    }
    __syncthreads();
    for (int i = tid; i < 4096; i += 256) {
        int n = i >> 6, k = i & 63;                 // write coalesced over k
        g_wot[n * 512 + k0 + k] = t[n][k];
    }
}

// ---------------------------------------------------------------------------
// Kernel 1: QKV projection, fp16 tensor cores (unchanged from R12).
// ---------------------------------------------------------------------------
#define QSTRD  72
#define WQSTRD 136

__global__ __launch_bounds__(256) void qkv_tc_kernel(
    const float* __restrict__ x,
    const float* __restrict__ Wq, const float* __restrict__ bq,
    const float* __restrict__ Wk, const float* __restrict__ bk,
    const float* __restrict__ Wv, const float* __restrict__ bv)
{
    const float* W; const float* bias; __half* out; float sc;
    if (blockIdx.z == 0)      { W = Wq; bias = bq; out = g_qh; sc = 0.180336880111120425f; }
    else if (blockIdx.z == 1) { W = Wk; bias = bk; out = g_kh; sc = 1.0f; }
    else                      { W = Wv; bias = bv; out = g_vh; sc = 1.0f; }

    __shared__ __half Xs[128 * QSTRD];   // [row][k]
    __shared__ __half Ws[64 * WQSTRD];   // [k][n]
    u32* Xsu = (u32*)Xs;

    const int row0 = blockIdx.x * 128;
    const int col0 = blockIdx.y * 128;
    const int tid  = threadIdx.x;

    for (int i = tid; i < 2048; i += 256) {
        int r = i >> 4, c4 = i & 15;
        float4 v = *(const float4*)&x[(row0 + r) * D_ + c4 * 4];
        uint2 st;
        st.x = pack_h2(v.x, v.y);
        st.y = pack_h2(v.z, v.w);
        *(uint2*)&Xsu[r * (QSTRD / 2) + c4 * 2] = st;
    }
    for (int i = tid; i < 2048; i += 256) {
        int k = i >> 5, c4 = i & 31;
        float4 v = *(const float4*)&W[k * HD_ + col0 + c4 * 4];
        uint2 st;
        st.x = pack_h2(v.x, v.y);
        st.y = pack_h2(v.z, v.w);
        *(uint2*)&Ws[k * WQSTRD + c4 * 4] = st;
    }
    __syncthreads();

    const int warp = tid >> 5, lane = tid & 31;
    const int wm = warp >> 1, wn = warp & 1;
    const int qr = lane >> 2, qc = lane & 3;

    const u32 abase = s2u(Xs) +
        (u32)(((wm * 32 + (lane & 15)) * QSTRD + (lane >> 4) * 8) * 2);
    const u32 bbase = s2u(Ws) +
        (u32)(((lane & 15) * WQSTRD + wn * 64 + (lane >> 4) * 8) * 2);

    float acc[2][8][4] = {};
    #pragma unroll
    for (int kk = 0; kk < 4; kk++) {
        u32 a0[4], a1[4];
        ldsm4(a0, abase + (u32)(kk * 16 * 2));
        ldsm4(a1, abase + (u32)((16 * QSTRD + kk * 16) * 2));
        #pragma unroll
        for (int ntp = 0; ntp < 4; ntp++) {
            u32 b[4];
            ldsm4t(b, bbase + (u32)((kk * 16 * WQSTRD + ntp * 16) * 2));
            mma_f16(acc[0][2 * ntp],     a0, b[0], b[1]);
            mma_f16(acc[0][2 * ntp + 1], a0, b[2], b[3]);
            mma_f16(acc[1][2 * ntp],     a1, b[0], b[1]);
            mma_f16(acc[1][2 * ntp + 1], a1, b[2], b[3]);
        }
    }

    #pragma unroll
    for (int nt = 0; nt < 8; nt++) {
        int col = col0 + wn * 64 + nt * 8 + 2 * qc;
        float2 bb = *(const float2*)&bias[col];
        #pragma unroll
        for (int mt = 0; mt < 2; mt++) {
            int r = row0 + wm * 32 + mt * 16 + qr;
            u32 lo = pack_h2((acc[mt][nt][0] + bb.x) * sc, (acc[mt][nt][1] + bb.y) * sc);
            u32 hi = pack_h2((acc[mt][nt][2] + bb.x) * sc, (acc[mt][nt][3] + bb.y) * sc);
            *(u32*)&out[ r      * HD_ + col] = lo;
            *(u32*)&out[(r + 8) * HD_ + col] = hi;
        }
    }
}

// ---------------------------------------------------------------------------
// Kernel 2: fp16 flash attention + FUSED out-projection/residual/LayerNorm.
// Each block's 128x64 slice tile = 16 COMPLETE global ctx rows, so the
// whole epilogue (ctx@Wo + bo + x, LN) is block-local. No ctx round-trip.
// ---------------------------------------------------------------------------
#define STRDH 72
#define SM_MAX 8.0f
#define EROW 584   // fp16 row stride of epilogue ctx tile (16 rows x 8*72+8)

__global__ __launch_bounds__(256, 2) void attn_tc_kernel(
    const float* __restrict__ x,
    const float* __restrict__ bo,
    const float* __restrict__ gamma,
    const float* __restrict__ beta,
    float* __restrict__ out)
{
    __shared__ __half KV[4][64 * STRDH];  // [0..1]=K dbl-buf, [2..3]=V dbl-buf
    __shared__ float sacc[16][68];

    const int gh = blockIdx.y;
    const int q0 = blockIdx.x * 128;
    const __half* qb = g_qh + gh * (S_ * D_);
    const __half* kb = g_kh + gh * (S_ * D_);
    const __half* vb = g_vh + gh * (S_ * D_);

    const int tid  = threadIdx.x;
    const int warp = tid >> 5, lane = tid & 31;
    const int qr = lane >> 2, qc = lane & 3;
    const int row0 = warp * 16;

    const u32 klrow = (u32)(((((lane >> 4) << 3) + (lane & 7)) * STRDH
                             + ((lane >> 3) & 1) * 8) * 2);
    const u32 vlrow = (u32)(((lane & 15) * STRDH + (lane >> 4) * 8) * 2);

    const u32 ksb[2] = { s2u(&KV[0][0]) + klrow, s2u(&KV[1][0]) + klrow };
    const u32 vsb[2] = { s2u(&KV[2][0]) + vlrow, s2u(&KV[3][0]) + vlrow };

    u32 qf[4][4];
    {
        const int r0 = (q0 + row0 + qr) * D_;
        const int r1 = (q0 + row0 + qr + 8) * D_;
        #pragma unroll
        for (int kk = 0; kk < 4; kk++) {
            int c = kk * 16 + 2 * qc;
            qf[kk][0] = *(const u32*)&qb[r0 + c];
            qf[kk][1] = *(const u32*)&qb[r1 + c];
            qf[kk][2] = *(const u32*)&qb[r0 + c + 8];
            qf[kk][3] = *(const u32*)&qb[r1 + c + 8];
        }
    }

    float o[8][4] = {};
    float lacc[4] = {};

    const int r0s = tid >> 3, s0s = tid & 7;
    const int r1s = r0s + 32, s1s = s0s;

    uint4 kr0, kr1, vr0, vr1;
    kr0 = *(const uint4*)&kb[r0s * D_ + s0s * 8];
    kr1 = *(const uint4*)&kb[r1s * D_ + s1s * 8];
    vr0 = *(const uint4*)&vb[r0s * D_ + s0s * 8];
    vr1 = *(const uint4*)&vb[r1s * D_ + s1s * 8];
    *(uint4*)&KV[0][r0s * STRDH + s0s * 8] = kr0;
    *(uint4*)&KV[0][r1s * STRDH + s1s * 8] = kr1;
    *(uint4*)&KV[2][r0s * STRDH + s0s * 8] = vr0;
    *(uint4*)&KV[2][r1s * STRDH + s1s * 8] = vr1;
    __syncthreads();

    const int NT = S_ / 64;
    for (int kt = 0; kt < NT; kt++) {
        const int c = kt & 1;
        if (kt + 1 < NT) {
            const int k0n = (kt + 1) * 64;
            kr0 = *(const uint4*)&kb[(k0n + r0s) * D_ + s0s * 8];
            kr1 = *(const uint4*)&kb[(k0n + r1s) * D_ + s1s * 8];
            vr0 = *(const uint4*)&vb[(k0n + r0s) * D_ + s0s * 8];
            vr1 = *(const uint4*)&vb[(k0n + r1s) * D_ + s1s * 8];
        }

        float s[8][4] = {};
        #pragma unroll
        for (int kk = 0; kk < 4; kk++) {
            #pragma unroll
            for (int ntp = 0; ntp < 4; ntp++) {
                u32 b[4];
                ldsm4(b, ksb[c] + (u32)((ntp * 16 * STRDH + kk * 16) * 2));
                mma_f16(s[2 * ntp],     qf[kk], b[0], b[1]);
                mma_f16(s[2 * ntp + 1], qf[kk], b[2], b[3]);
            }
        }

        u32 pa[8][2];
        #pragma unroll
        for (int nt = 0; nt < 8; nt++) {
            pa[nt][0] = ex2_h2(s[nt][0] - SM_MAX, s[nt][1] - SM_MAX);
            pa[nt][1] = ex2_h2(s[nt][2] - SM_MAX, s[nt][3] - SM_MAX);
        }

        #pragma unroll
        for (int kk = 0; kk < 4; kk++) {
            u32 a[4] = { pa[2 * kk][0], pa[2 * kk][1],
                         pa[2 * kk + 1][0], pa[2 * kk + 1][1] };
            mma_f16(lacc, a, ONES_H2, ONES_H2);
            #pragma unroll
            for (int ntp = 0; ntp < 4; ntp++) {
                u32 b[4];
                ldsm4t(b, vsb[c] + (u32)((kk * 16 * STRDH + ntp * 16) * 2));
                mma_f16(o[2 * ntp],     a, b[0], b[1]);
                mma_f16(o[2 * ntp + 1], a, b[2], b[3]);
            }
        }

        if (kt + 1 < NT) {
            const int nb = 1 - c;
            *(uint4*)&KV[nb][r0s * STRDH + s0s * 8] = kr0;
            *(uint4*)&KV[nb][r1s * STRDH + s1s * 8] = kr1;
            *(uint4*)&KV[2 + nb][r0s * STRDH + s0s * 8] = vr0;
            *(uint4*)&KV[2 + nb][r1s * STRDH + s1s * 8] = vr1;
        }
        __syncthreads();
    }

    // =======================================================================
    // FUSED EPILOGUE
    // Slice rows 8R..8R+7 of this block are the 8 64-col chunks of global ctx
    // row R. Warp w's 16 slice rows = global rows (2w, 2w+1) complete.
    // =======================================================================
    __half* ctxg = (__half*)&KV[0][0];   // 16 rows x EROW fp16 (18.7 KB < 36.9)

    // ---- O /= l, pack into ctx-global layout: ctxg[r][j*72 + d] ----
    float inv0 = 1.f / lacc[0], inv1 = 1.f / lacc[2];
    #pragma unroll
    for (int nt = 0; nt < 8; nt++) {
        int coff = qr * 72 + nt * 8 + 2 * qc;   // chunk j = qr, d = nt*8+2qc
        *(u32*)&ctxg[(2 * warp    ) * EROW + coff] = pack_h2(o[nt][0] * inv0, o[nt][1] * inv0);
        *(u32*)&ctxg[(2 * warp + 1) * EROW + coff] = pack_h2(o[nt][2] * inv1, o[nt][3] * inv1);
    }
    for (int i = tid; i < 16 * 68; i += 256) (&sacc[0][0])[i] = 0.f;
    __syncthreads();

    // ---- partial GEMM: D[16,64] += ctxg[16, k-chunk w] @ WoT^T ----
    const u32 eabase = s2u(ctxg) +
        (u32)((((lane & 15) * EROW) + warp * 72 + ((lane >> 4) * 8)) * 2);
    const int k0w = warp * 64;
    float ep[8][4] = {};
    #pragma unroll
    for (int kk = 0; kk < 4; kk++) {
        u32 a[4];
        ldsm4(a, eabase + (u32)(kk * 16 * 2));
        #pragma unroll
        for (int nt = 0; nt < 8; nt++) {
            const __half* wp = &g_wot[(nt * 8 + qr) * 512 + k0w + kk * 16 + 2 * qc];
            u32 b0 = *(const u32*)wp;
            u32 b1 = *(const u32*)(wp + 8);
            mma_f16(ep[nt], a, b0, b1);
        }
    }
    #pragma unroll
    for (int nt = 0; nt < 8; nt++) {
        atomicAdd(&sacc[qr    ][nt * 8 + 2 * qc    ], ep[nt][0]);
        atomicAdd(&sacc[qr    ][nt * 8 + 2 * qc + 1], ep[nt][1]);
        atomicAdd(&sacc[qr + 8][nt * 8 + 2 * qc    ], ep[nt][2]);
        atomicAdd(&sacc[qr + 8][nt * 8 + 2 * qc + 1], ep[nt][3]);
    }
    __syncthreads();

    // ---- + bias + residual, LayerNorm(64), write out. 16 threads / row ----
    {
        const int r = tid >> 4, t16 = tid & 15;
        const int Rg = gh * 256 + blockIdx.x * 16 + r;   // global row
        const int col = t16 * 4;
        float4 xa = *(const float4*)&x[Rg * D_ + col];
        float4 ba = *(const float4*)&bo[col];
        float y0 = sacc[r][col    ] + ba.x + xa.x;
        float y1 = sacc[r][col + 1] + ba.y + xa.y;
        float y2 = sacc[r][col + 2] + ba.z + xa.z;
        float y3 = sacc[r][col + 3] + ba.w + xa.w;
        float sm = y0 + y1 + y2 + y3;
        float sq = y0 * y0 + y1 * y1 + y2 * y2 + y3 * y3;
        #pragma unroll
        for (int off = 8; off; off >>= 1) {
            sm += __shfl_xor_sync(0xffffffffu, sm, off, 16);
            sq += __shfl_xor_sync(0xffffffffu, sq, off, 16);
        }
        float mu  = sm * (1.f / 64.f);
        float inv = rsqrtf(sq * (1.f / 64.f) - mu * mu + 1e-5f);
        float4 gm = *(const float4*)&gamma[col];
        float4 be = *(const float4*)&beta[col];
        float4 ov;
        ov.x = (y0 - mu) * inv * gm.x + be.x;
        ov.y = (y1 - mu) * inv * gm.y + be.y;
        ov.z = (y2 - mu) * inv * gm.z + be.z;
        ov.w = (y3 - mu) * inv * gm.w + be.w;
        *(float4*)&out[Rg * D_ + col] = ov;
    }
}

// ---------------------------------------------------------------------------
extern "C" void kernel_launch(void* const* d_in, const int* in_sizes, int n_in,
                              void* d_out, int out_size)
{
    const float* x     = (const float*)d_in[0];
    const float* Wq    = (const float*)d_in[1];
    const float* bq    = (const float*)d_in[2];
    const float* Wk    = (const float*)d_in[3];
    const float* bk    = (const float*)d_in[4];
    const float* Wv    = (const float*)d_in[5];
    const float* bv    = (const float*)d_in[6];
    const float* Wo    = (const float*)d_in[7];
    const float* bo    = (const float*)d_in[8];
    const float* gamma = (const float*)d_in[9];
    const float* beta  = (const float*)d_in[10];
    float* out = (float*)d_out;

    wo_prep<<<8, 256>>>(Wo);

    dim3 g1(BS_ / 128, HD_ / 128, 3);
    qkv_tc_kernel<<<g1, 256>>>(x, Wq, bq, Wk, bk, Wv, bv);

    dim3 g2(S_ / 128, GH_);
    attn_tc_kernel<<<g2, 256>>>(x, bo, gamma, beta, out);
}

// round 14
// speedup vs baseline: 1.0595x; 1.0595x over previous
#include <cuda_runtime.h>
#include <cuda_fp16.h>
#include <cstdint>
#include <math.h>

using u32 = unsigned int;

#define B_  8
#define S_  2048
#define D_  64
#define H_  8
#define HD_ 512
#define BS_ (B_ * S_)       // 16384 rows
#define GH_ (B_ * H_)       // 64 "batch-heads" in the flat view
#define NTOT_ (BS_ * HD_)   // 8388608 elements per QKV buffer

// Scratch (device globals — no allocation allowed in kernel_launch)
__device__ __half g_qh[NTOT_];        // Q pre-scaled by log2(e)/8
__device__ __half g_kh[NTOT_];
__device__ __half g_vh[NTOT_];
__device__ __half g_wot[64 * 512];    // Wo transposed [n][k], fp16

#define ONES_H2 0x3C003C00u     // half2(1.0, 1.0)

// ---------------------------------------------------------------------------
// helpers
// ---------------------------------------------------------------------------
__device__ __forceinline__ u32 pack_h2(float a, float b) {
    __half2 h = __floats2half2_rn(a, b);
    return *(u32*)&h;
}

__device__ __forceinline__ u32 ex2_h2(float a, float b) {
    __half2 h = __floats2half2_rn(a, b);
    u32 x = *(u32*)&h, y;
    asm("ex2.approx.f16x2 %0, %1;" : "=r"(y) : "r"(x));
    return y;
}

__device__ __forceinline__ u32 s2u(const void* p) {
    return (u32)__cvta_generic_to_shared(p);
}

__device__ __forceinline__ void ldsm4(u32 r[4], u32 addr) {
    asm volatile("ldmatrix.sync.aligned.m8n8.x4.shared.b16 {%0,%1,%2,%3}, [%4];"
                 : "=r"(r[0]), "=r"(r[1]), "=r"(r[2]), "=r"(r[3]) : "r"(addr));
}

__device__ __forceinline__ void ldsm4t(u32 r[4], u32 addr) {
    asm volatile("ldmatrix.sync.aligned.m8n8.x4.trans.shared.b16 {%0,%1,%2,%3}, [%4];"
                 : "=r"(r[0]), "=r"(r[1]), "=r"(r[2]), "=r"(r[3]) : "r"(addr));
}

__device__ __forceinline__ void mma_f16(float c[4], const u32 a[4],
                                        const u32 b0, const u32 b1) {
    asm volatile(
        "mma.sync.aligned.m16n8k16.row.col.f32.f16.f16.f32 "
        "{%0,%1,%2,%3}, {%4,%5,%6,%7}, {%8,%9}, {%0,%1,%2,%3};"
        : "+f"(c[0]), "+f"(c[1]), "+f"(c[2]), "+f"(c[3])
        : "r"(a[0]), "r"(a[1]), "r"(a[2]), "r"(a[3]), "r"(b0), "r"(b1));
}

// ---------------------------------------------------------------------------
// Kernel 0: Wo -> fp16 transposed [n][k]. Grid (8,4): 32 blocks.
// ---------------------------------------------------------------------------
__global__ void wo_prep(const float* __restrict__ Wo)
{
    __shared__ __half t[16][72];
    const int k0 = blockIdx.x * 64;
    const int n0 = blockIdx.y * 16;
    const int tid = threadIdx.x;
    for (int i = tid; i < 1024; i += 256) {
        int k = i >> 4, n = i & 15;                 // read 16-wide over n
        t[n][k] = __float2half(Wo[(k0 + k) * D_ + n0 + n]);
    }
    __syncthreads();
    for (int i = tid; i < 1024; i += 256) {
        int n = i >> 6, k = i & 63;                 // write coalesced over k
        g_wot[(n0 + n) * 512 + k0 + k] = t[n][k];
    }
}

// ---------------------------------------------------------------------------
// Kernel 1: QKV projection, fp16 tensor cores (unchanged).
// ---------------------------------------------------------------------------
#define QSTRD  72
#define WQSTRD 136

__global__ __launch_bounds__(256) void qkv_tc_kernel(
    const float* __restrict__ x,
    const float* __restrict__ Wq, const float* __restrict__ bq,
    const float* __restrict__ Wk, const float* __restrict__ bk,
    const float* __restrict__ Wv, const float* __restrict__ bv)
{
    const float* W; const float* bias; __half* out; float sc;
    if (blockIdx.z == 0)      { W = Wq; bias = bq; out = g_qh; sc = 0.180336880111120425f; }
    else if (blockIdx.z == 1) { W = Wk; bias = bk; out = g_kh; sc = 1.0f; }
    else                      { W = Wv; bias = bv; out = g_vh; sc = 1.0f; }

    __shared__ __half Xs[128 * QSTRD];   // [row][k]
    __shared__ __half Ws[64 * WQSTRD];   // [k][n]
    u32* Xsu = (u32*)Xs;

    const int row0 = blockIdx.x * 128;
    const int col0 = blockIdx.y * 128;
    const int tid  = threadIdx.x;

    for (int i = tid; i < 2048; i += 256) {
        int r = i >> 4, c4 = i & 15;
        float4 v = *(const float4*)&x[(row0 + r) * D_ + c4 * 4];
        uint2 st;
        st.x = pack_h2(v.x, v.y);
        st.y = pack_h2(v.z, v.w);
        *(uint2*)&Xsu[r * (QSTRD / 2) + c4 * 2] = st;
    }
    for (int i = tid; i < 2048; i += 256) {
        int k = i >> 5, c4 = i & 31;
        float4 v = *(const float4*)&W[k * HD_ + col0 + c4 * 4];
        uint2 st;
        st.x = pack_h2(v.x, v.y);
        st.y = pack_h2(v.z, v.w);
        *(uint2*)&Ws[k * WQSTRD + c4 * 4] = st;
    }
    __syncthreads();

    const int warp = tid >> 5, lane = tid & 31;
    const int wm = warp >> 1, wn = warp & 1;
    const int qr = lane >> 2, qc = lane & 3;

    const u32 abase = s2u(Xs) +
        (u32)(((wm * 32 + (lane & 15)) * QSTRD + (lane >> 4) * 8) * 2);
    const u32 bbase = s2u(Ws) +
        (u32)(((lane & 15) * WQSTRD + wn * 64 + (lane >> 4) * 8) * 2);

    float acc[2][8][4] = {};
    #pragma unroll
    for (int kk = 0; kk < 4; kk++) {
        u32 a0[4], a1[4];
        ldsm4(a0, abase + (u32)(kk * 16 * 2));
        ldsm4(a1, abase + (u32)((16 * QSTRD + kk * 16) * 2));
        #pragma unroll
        for (int ntp = 0; ntp < 4; ntp++) {
            u32 b[4];
            ldsm4t(b, bbase + (u32)((kk * 16 * WQSTRD + ntp * 16) * 2));
            mma_f16(acc[0][2 * ntp],     a0, b[0], b[1]);
            mma_f16(acc[0][2 * ntp + 1], a0, b[2], b[3]);
            mma_f16(acc[1][2 * ntp],     a1, b[0], b[1]);
            mma_f16(acc[1][2 * ntp + 1], a1, b[2], b[3]);
        }
    }

    #pragma unroll
    for (int nt = 0; nt < 8; nt++) {
        int col = col0 + wn * 64 + nt * 8 + 2 * qc;
        float2 bb = *(const float2*)&bias[col];
        #pragma unroll
        for (int mt = 0; mt < 2; mt++) {
            int r = row0 + wm * 32 + mt * 16 + qr;
            u32 lo = pack_h2((acc[mt][nt][0] + bb.x) * sc, (acc[mt][nt][1] + bb.y) * sc);
            u32 hi = pack_h2((acc[mt][nt][2] + bb.x) * sc, (acc[mt][nt][3] + bb.y) * sc);
            *(u32*)&out[ r      * HD_ + col] = lo;
            *(u32*)&out[(r + 8) * HD_ + col] = hi;
        }
    }
}

// ---------------------------------------------------------------------------
// Kernel 2: fp16 flash attention + FUSED out-projection/residual/LayerNorm.
// Epilogue GEMM: warp w owns output n-tile w across all K=512; Wo chunks
// staged to smem (overlaid on dead KV buffers); ldsm operands; NO atomics.
// ---------------------------------------------------------------------------
#define STRDH 72
#define SM_MAX 8.0f
#define EROW 584     // ctxg row stride (halves): 8*72 + 8; /2 mod 32 = 4
#define WT2STRD 136  // staged WoT chunk stride (halves): 128 + 8

__global__ __launch_bounds__(256, 2) void attn_tc_kernel(
    const float* __restrict__ x,
    const float* __restrict__ bo,
    const float* __restrict__ gamma,
    const float* __restrict__ beta,
    float* __restrict__ out)
{
    __shared__ __half KV[4][64 * STRDH];  // [0..1]=K dbl-buf, [2..3]=V dbl-buf
    __shared__ float sacc[16][68];

    const int gh = blockIdx.y;
    const int q0 = blockIdx.x * 128;
    const __half* qb = g_qh + gh * (S_ * D_);
    const __half* kb = g_kh + gh * (S_ * D_);
    const __half* vb = g_vh + gh * (S_ * D_);

    const int tid  = threadIdx.x;
    const int warp = tid >> 5, lane = tid & 31;
    const int qr = lane >> 2, qc = lane & 3;
    const int row0 = warp * 16;

    const u32 klrow = (u32)(((((lane >> 4) << 3) + (lane & 7)) * STRDH
                             + ((lane >> 3) & 1) * 8) * 2);
    const u32 vlrow = (u32)(((lane & 15) * STRDH + (lane >> 4) * 8) * 2);

    const u32 ksb[2] = { s2u(&KV[0][0]) + klrow, s2u(&KV[1][0]) + klrow };
    const u32 vsb[2] = { s2u(&KV[2][0]) + vlrow, s2u(&KV[3][0]) + vlrow };

    u32 qf[4][4];
    {
        const int r0 = (q0 + row0 + qr) * D_;
        const int r1 = (q0 + row0 + qr + 8) * D_;
        #pragma unroll
        for (int kk = 0; kk < 4; kk++) {
            int c = kk * 16 + 2 * qc;
            qf[kk][0] = *(const u32*)&qb[r0 + c];
            qf[kk][1] = *(const u32*)&qb[r1 + c];
            qf[kk][2] = *(const u32*)&qb[r0 + c + 8];
            qf[kk][3] = *(const u32*)&qb[r1 + c + 8];
        }
    }

    float o[8][4] = {};
    float lacc[4] = {};

    const int r0s = tid >> 3, s0s = tid & 7;
    const int r1s = r0s + 32, s1s = s0s;

    uint4 kr0, kr1, vr0, vr1;
    kr0 = *(const uint4*)&kb[r0s * D_ + s0s * 8];
    kr1 = *(const uint4*)&kb[r1s * D_ + s1s * 8];
    vr0 = *(const uint4*)&vb[r0s * D_ + s0s * 8];
    vr1 = *(const uint4*)&vb[r1s * D_ + s1s * 8];
    *(uint4*)&KV[0][r0s * STRDH + s0s * 8] = kr0;
    *(uint4*)&KV[0][r1s * STRDH + s1s * 8] = kr1;
    *(uint4*)&KV[2][r0s * STRDH + s0s * 8] = vr0;
    *(uint4*)&KV[2][r1s * STRDH + s1s * 8] = vr1;
    __syncthreads();

    const int NT = S_ / 64;
    for (int kt = 0; kt < NT; kt++) {
        const int c = kt & 1;
        if (kt + 1 < NT) {
            const int k0n = (kt + 1) * 64;
            kr0 = *(const uint4*)&kb[(k0n + r0s) * D_ + s0s * 8];
            kr1 = *(const uint4*)&kb[(k0n + r1s) * D_ + s1s * 8];
            vr0 = *(const uint4*)&vb[(k0n + r0s) * D_ + s0s * 8];
            vr1 = *(const uint4*)&vb[(k0n + r1s) * D_ + s1s * 8];
        }

        float s[8][4] = {};
        #pragma unroll
        for (int kk = 0; kk < 4; kk++) {
            #pragma unroll
            for (int ntp = 0; ntp < 4; ntp++) {
                u32 b[4];
                ldsm4(b, ksb[c] + (u32)((ntp * 16 * STRDH + kk * 16) * 2));
                mma_f16(s[2 * ntp],     qf[kk], b[0], b[1]);
                mma_f16(s[2 * ntp + 1], qf[kk], b[2], b[3]);
            }
        }

        u32 pa[8][2];
        #pragma unroll
        for (int nt = 0; nt < 8; nt++) {
            pa[nt][0] = ex2_h2(s[nt][0] - SM_MAX, s[nt][1] - SM_MAX);
            pa[nt][1] = ex2_h2(s[nt][2] - SM_MAX, s[nt][3] - SM_MAX);
        }

        #pragma unroll
        for (int kk = 0; kk < 4; kk++) {
            u32 a[4] = { pa[2 * kk][0], pa[2 * kk][1],
                         pa[2 * kk + 1][0], pa[2 * kk + 1][1] };
            mma_f16(lacc, a, ONES_H2, ONES_H2);
            #pragma unroll
            for (int ntp = 0; ntp < 4; ntp++) {
                u32 b[4];
                ldsm4t(b, vsb[c] + (u32)((kk * 16 * STRDH + ntp * 16) * 2));
                mma_f16(o[2 * ntp],     a, b[0], b[1]);
                mma_f16(o[2 * ntp + 1], a, b[2], b[3]);
            }
        }

        if (kt + 1 < NT) {
            const int nb = 1 - c;
            *(uint4*)&KV[nb][r0s * STRDH + s0s * 8] = kr0;
            *(uint4*)&KV[nb][r1s * STRDH + s1s * 8] = kr1;
            *(uint4*)&KV[2 + nb][r0s * STRDH + s0s * 8] = vr0;
            *(uint4*)&KV[2 + nb][r1s * STRDH + s1s * 8] = vr1;
        }
        __syncthreads();
    }

    // =======================================================================
    // FUSED EPILOGUE (v2): ctxg 16xEROW + staged WoT chunk, both in dead KV.
    // Warp w computes D[16, cols 8w..8w+7] over all K=512. No atomics.
    // =======================================================================
    __half* ctxg = (__half*)&KV[0][0];          // 16 * EROW halves (18688 B)
    __half* wt2  = ctxg + 16 * EROW;            // 64 * WT2STRD halves (17408 B)

    // ---- O /= l, pack into ctx-global layout: ctxg[r][j*72 + d], j = qr ----
    float inv0 = 1.f / lacc[0], inv1 = 1.f / lacc[2];
    #pragma unroll
    for (int nt = 0; nt < 8; nt++) {
        int coff = qr * 72 + nt * 8 + 2 * qc;
        *(u32*)&ctxg[(2 * warp    ) * EROW + coff] = pack_h2(o[nt][0] * inv0, o[nt][1] * inv0);
        *(u32*)&ctxg[(2 * warp + 1) * EROW + coff] = pack_h2(o[nt][2] * inv1, o[nt][3] * inv1);
    }

    const u32 actx = s2u(ctxg) +
        (u32)((((lane & 15) * EROW) + ((lane >> 4) * 8)) * 2);
    const u32 bwt = s2u(wt2) +
        (u32)((((warp * 8 + (lane & 7)) * WT2STRD) + ((lane >> 3) * 8)) * 2);

    float ec[4] = {};
    #pragma unroll
    for (int kq = 0; kq < 4; kq++) {
        if (kq) __syncthreads();            // prior ldsm reads done before overwrite
        #pragma unroll
        for (int t = 0; t < 4; t++) {
            int i = tid + t * 256;
            int n = i >> 4, c16 = i & 15;
            *(uint4*)&wt2[n * WT2STRD + c16 * 8] =
                *(const uint4*)&g_wot[n * 512 + kq * 128 + c16 * 8];
        }
        __syncthreads();

        u32 bf[4][4];
        #pragma unroll
        for (int kk2 = 0; kk2 < 4; kk2++)
            ldsm4(bf[kk2], bwt + (u32)(kk2 * 64));   // 32 halves = 64 bytes
        #pragma unroll
        for (int kk = 0; kk < 8; kk++) {
            u32 a[4];
            int aoff = kq * 144 + (kk >> 2) * 72 + (kk & 3) * 16;
            ldsm4(a, actx + (u32)(aoff * 2));
            mma_f16(ec, a, bf[kk >> 1][(kk & 1) * 2], bf[kk >> 1][(kk & 1) * 2 + 1]);
        }
    }

    *(float2*)&sacc[qr    ][warp * 8 + 2 * qc] = make_float2(ec[0], ec[1]);
    *(float2*)&sacc[qr + 8][warp * 8 + 2 * qc] = make_float2(ec[2], ec[3]);
    __syncthreads();

    // ---- + bias + residual, LayerNorm(64), write out. 16 threads / row ----
    {
        const int r = tid >> 4, t16 = tid & 15;
        const int Rg = gh * 256 + blockIdx.x * 16 + r;   // global row
        const int col = t16 * 4;
        float4 xa = *(const float4*)&x[Rg * D_ + col];
        float4 ba = *(const float4*)&bo[col];
        float y0 = sacc[r][col    ] + ba.x + xa.x;
        float y1 = sacc[r][col + 1] + ba.y + xa.y;
        float y2 = sacc[r][col + 2] + ba.z + xa.z;
        float y3 = sacc[r][col + 3] + ba.w + xa.w;
        float sm = y0 + y1 + y2 + y3;
        float sq = y0 * y0 + y1 * y1 + y2 * y2 + y3 * y3;
        #pragma unroll
        for (int off = 8; off; off >>= 1) {
            sm += __shfl_xor_sync(0xffffffffu, sm, off, 16);
            sq += __shfl_xor_sync(0xffffffffu, sq, off, 16);
        }
        float mu  = sm * (1.f / 64.f);
        float inv = rsqrtf(sq * (1.f / 64.f) - mu * mu + 1e-5f);
        float4 gm = *(const float4*)&gamma[col];
        float4 be = *(const float4*)&beta[col];
        float4 ov;
        ov.x = (y0 - mu) * inv * gm.x + be.x;
        ov.y = (y1 - mu) * inv * gm.y + be.y;
        ov.z = (y2 - mu) * inv * gm.z + be.z;
        ov.w = (y3 - mu) * inv * gm.w + be.w;
        *(float4*)&out[Rg * D_ + col] = ov;
    }
}

// ---------------------------------------------------------------------------
extern "C" void kernel_launch(void* const* d_in, const int* in_sizes, int n_in,
                              void* d_out, int out_size)
{
    const float* x     = (const float*)d_in[0];
    const float* Wq    = (const float*)d_in[1];
    const float* bq    = (const float*)d_in[2];
    const float* Wk    = (const float*)d_in[3];
    const float* bk    = (const float*)d_in[4];
    const float* Wv    = (const float*)d_in[5];
    const float* bv    = (const float*)d_in[6];
    const float* Wo    = (const float*)d_in[7];
    const float* bo    = (const float*)d_in[8];
    const float* gamma = (const float*)d_in[9];
    const float* beta  = (const float*)d_in[10];
    float* out = (float*)d_out;

    wo_prep<<<dim3(8, 4), 256>>>(Wo);

    dim3 g1(BS_ / 128, HD_ / 128, 3);
    qkv_tc_kernel<<<g1, 256>>>(x, Wq, bq, Wk, bk, Wv, bv);

    dim3 g2(S_ / 128, GH_);
    attn_tc_kernel<<<g2, 256>>>(x, bo, gamma, beta, out);
}

// round 15
// speedup vs baseline: 1.0891x; 1.0279x over previous
#include <cuda_runtime.h>
#include <cuda_fp16.h>
#include <cstdint>
#include <math.h>

using u32 = unsigned int;

#define B_  8
#define S_  2048
#define D_  64
#define H_  8
#define HD_ 512
#define BS_ (B_ * S_)       // 16384 rows
#define GH_ (B_ * H_)       // 64 "batch-heads" in the flat view
#define NTOT_ (BS_ * HD_)   // 8388608 elements per QKV buffer

// Scratch (device globals — no allocation allowed in kernel_launch)
__device__ __half g_qh[NTOT_];        // Q pre-scaled by log2(e)/8
__device__ __half g_kh[NTOT_];
__device__ __half g_vh[NTOT_];
__device__ uint2  g_wop[8192];        // Wo pre-packed as epilogue B-fragments
                                      // index = (warp*32 + kk)*32 + lane

#define ONES_H2 0x3C003C00u     // half2(1.0, 1.0)

// ---------------------------------------------------------------------------
// helpers
// ---------------------------------------------------------------------------
__device__ __forceinline__ u32 pack_h2(float a, float b) {
    __half2 h = __floats2half2_rn(a, b);
    return *(u32*)&h;
}

__device__ __forceinline__ u32 ex2_h2(float a, float b) {
    __half2 h = __floats2half2_rn(a, b);
    u32 x = *(u32*)&h, y;
    asm("ex2.approx.f16x2 %0, %1;" : "=r"(y) : "r"(x));
    return y;
}

__device__ __forceinline__ u32 s2u(const void* p) {
    return (u32)__cvta_generic_to_shared(p);
}

__device__ __forceinline__ void ldsm4(u32 r[4], u32 addr) {
    asm volatile("ldmatrix.sync.aligned.m8n8.x4.shared.b16 {%0,%1,%2,%3}, [%4];"
                 : "=r"(r[0]), "=r"(r[1]), "=r"(r[2]), "=r"(r[3]) : "r"(addr));
}

__device__ __forceinline__ void ldsm4t(u32 r[4], u32 addr) {
    asm volatile("ldmatrix.sync.aligned.m8n8.x4.trans.shared.b16 {%0,%1,%2,%3}, [%4];"
                 : "=r"(r[0]), "=r"(r[1]), "=r"(r[2]), "=r"(r[3]) : "r"(addr));
}

__device__ __forceinline__ void mma_f16(float c[4], const u32 a[4],
                                        const u32 b0, const u32 b1) {
    asm volatile(
        "mma.sync.aligned.m16n8k16.row.col.f32.f16.f16.f32 "
        "{%0,%1,%2,%3}, {%4,%5,%6,%7}, {%8,%9}, {%0,%1,%2,%3};"
        : "+f"(c[0]), "+f"(c[1]), "+f"(c[2]), "+f"(c[3])
        : "r"(a[0]), "r"(a[1]), "r"(a[2]), "r"(a[3]), "r"(b0), "r"(b1));
}

// ---------------------------------------------------------------------------
// Kernel 0: Wo -> epilogue B-fragment layout.
// For warp w, mma step kk, lane (qr,qc):
//   b0 = {Wo[k][n], Wo[k+1][n]},  b1 = {Wo[k+8][n], Wo[k+9][n]}
//   with n = 8w + qr, k = 16kk + 2qc.
// ---------------------------------------------------------------------------
__global__ void wo_prep(const float* __restrict__ Wo)
{
    int e = blockIdx.x * 256 + threadIdx.x;       // 0..8191
    int lane = e & 31;
    int kk   = (e >> 5) & 31;
    int w    = e >> 10;
    int qr = lane >> 2, qc = lane & 3;
    int n = w * 8 + qr;
    int k = kk * 16 + 2 * qc;
    u32 b0 = pack_h2(Wo[ k      * D_ + n], Wo[(k + 1) * D_ + n]);
    u32 b1 = pack_h2(Wo[(k + 8) * D_ + n], Wo[(k + 9) * D_ + n]);
    g_wop[e] = make_uint2(b0, b1);
}

// ---------------------------------------------------------------------------
// Kernel 1: QKV projection, fp16 tensor cores (unchanged).
// ---------------------------------------------------------------------------
#define QSTRD  72
#define WQSTRD 136

__global__ __launch_bounds__(256) void qkv_tc_kernel(
    const float* __restrict__ x,
    const float* __restrict__ Wq, const float* __restrict__ bq,
    const float* __restrict__ Wk, const float* __restrict__ bk,
    const float* __restrict__ Wv, const float* __restrict__ bv)
{
    const float* W; const float* bias; __half* out; float sc;
    if (blockIdx.z == 0)      { W = Wq; bias = bq; out = g_qh; sc = 0.180336880111120425f; }
    else if (blockIdx.z == 1) { W = Wk; bias = bk; out = g_kh; sc = 1.0f; }
    else                      { W = Wv; bias = bv; out = g_vh; sc = 1.0f; }

    __shared__ __half Xs[128 * QSTRD];   // [row][k]
    __shared__ __half Ws[64 * WQSTRD];   // [k][n]
    u32* Xsu = (u32*)Xs;

    const int row0 = blockIdx.x * 128;
    const int col0 = blockIdx.y * 128;
    const int tid  = threadIdx.x;

    for (int i = tid; i < 2048; i += 256) {
        int r = i >> 4, c4 = i & 15;
        float4 v = *(const float4*)&x[(row0 + r) * D_ + c4 * 4];
        uint2 st;
        st.x = pack_h2(v.x, v.y);
        st.y = pack_h2(v.z, v.w);
        *(uint2*)&Xsu[r * (QSTRD / 2) + c4 * 2] = st;
    }
    for (int i = tid; i < 2048; i += 256) {
        int k = i >> 5, c4 = i & 31;
        float4 v = *(const float4*)&W[k * HD_ + col0 + c4 * 4];
        uint2 st;
        st.x = pack_h2(v.x, v.y);
        st.y = pack_h2(v.z, v.w);
        *(uint2*)&Ws[k * WQSTRD + c4 * 4] = st;
    }
    __syncthreads();

    const int warp = tid >> 5, lane = tid & 31;
    const int wm = warp >> 1, wn = warp & 1;
    const int qr = lane >> 2, qc = lane & 3;

    const u32 abase = s2u(Xs) +
        (u32)(((wm * 32 + (lane & 15)) * QSTRD + (lane >> 4) * 8) * 2);
    const u32 bbase = s2u(Ws) +
        (u32)(((lane & 15) * WQSTRD + wn * 64 + (lane >> 4) * 8) * 2);

    float acc[2][8][4] = {};
    #pragma unroll
    for (int kk = 0; kk < 4; kk++) {
        u32 a0[4], a1[4];
        ldsm4(a0, abase + (u32)(kk * 16 * 2));
        ldsm4(a1, abase + (u32)((16 * QSTRD + kk * 16) * 2));
        #pragma unroll
        for (int ntp = 0; ntp < 4; ntp++) {
            u32 b[4];
            ldsm4t(b, bbase + (u32)((kk * 16 * WQSTRD + ntp * 16) * 2));
            mma_f16(acc[0][2 * ntp],     a0, b[0], b[1]);
            mma_f16(acc[0][2 * ntp + 1], a0, b[2], b[3]);
            mma_f16(acc[1][2 * ntp],     a1, b[0], b[1]);
            mma_f16(acc[1][2 * ntp + 1], a1, b[2], b[3]);
        }
    }

    #pragma unroll
    for (int nt = 0; nt < 8; nt++) {
        int col = col0 + wn * 64 + nt * 8 + 2 * qc;
        float2 bb = *(const float2*)&bias[col];
        #pragma unroll
        for (int mt = 0; mt < 2; mt++) {
            int r = row0 + wm * 32 + mt * 16 + qr;
            u32 lo = pack_h2((acc[mt][nt][0] + bb.x) * sc, (acc[mt][nt][1] + bb.y) * sc);
            u32 hi = pack_h2((acc[mt][nt][2] + bb.x) * sc, (acc[mt][nt][3] + bb.y) * sc);
            *(u32*)&out[ r      * HD_ + col] = lo;
            *(u32*)&out[(r + 8) * HD_ + col] = hi;
        }
    }
}

// ---------------------------------------------------------------------------
// Kernel 2: fp16 flash attention + FUSED epilogue (v3: zero staging, 1 sync).
// Epilogue B-fragments come straight from g_wop via coalesced LDG.64.
// ---------------------------------------------------------------------------
#define STRDH 72
#define SM_MAX 8.0f
#define EROW 584     // ctxg row stride (halves): 8*72 + 8

__global__ __launch_bounds__(256, 2) void attn_tc_kernel(
    const float* __restrict__ x,
    const float* __restrict__ bo,
    const float* __restrict__ gamma,
    const float* __restrict__ beta,
    float* __restrict__ out)
{
    __shared__ __half KV[4][64 * STRDH];  // [0..1]=K dbl-buf, [2..3]=V dbl-buf
    __shared__ float sacc[16][68];

    const int gh = blockIdx.y;
    const int q0 = blockIdx.x * 128;
    const __half* qb = g_qh + gh * (S_ * D_);
    const __half* kb = g_kh + gh * (S_ * D_);
    const __half* vb = g_vh + gh * (S_ * D_);

    const int tid  = threadIdx.x;
    const int warp = tid >> 5, lane = tid & 31;
    const int qr = lane >> 2, qc = lane & 3;
    const int row0 = warp * 16;

    const u32 klrow = (u32)(((((lane >> 4) << 3) + (lane & 7)) * STRDH
                             + ((lane >> 3) & 1) * 8) * 2);
    const u32 vlrow = (u32)(((lane & 15) * STRDH + (lane >> 4) * 8) * 2);

    const u32 ksb[2] = { s2u(&KV[0][0]) + klrow, s2u(&KV[1][0]) + klrow };
    const u32 vsb[2] = { s2u(&KV[2][0]) + vlrow, s2u(&KV[3][0]) + vlrow };

    u32 qf[4][4];
    {
        const int r0 = (q0 + row0 + qr) * D_;
        const int r1 = (q0 + row0 + qr + 8) * D_;
        #pragma unroll
        for (int kk = 0; kk < 4; kk++) {
            int c = kk * 16 + 2 * qc;
            qf[kk][0] = *(const u32*)&qb[r0 + c];
            qf[kk][1] = *(const u32*)&qb[r1 + c];
            qf[kk][2] = *(const u32*)&qb[r0 + c + 8];
            qf[kk][3] = *(const u32*)&qb[r1 + c + 8];
        }
    }

    float o[8][4] = {};
    float lacc[4] = {};

    const int r0s = tid >> 3, s0s = tid & 7;
    const int r1s = r0s + 32, s1s = s0s;

    uint4 kr0, kr1, vr0, vr1;
    kr0 = *(const uint4*)&kb[r0s * D_ + s0s * 8];
    kr1 = *(const uint4*)&kb[r1s * D_ + s1s * 8];
    vr0 = *(const uint4*)&vb[r0s * D_ + s0s * 8];
    vr1 = *(const uint4*)&vb[r1s * D_ + s1s * 8];
    *(uint4*)&KV[0][r0s * STRDH + s0s * 8] = kr0;
    *(uint4*)&KV[0][r1s * STRDH + s1s * 8] = kr1;
    *(uint4*)&KV[2][r0s * STRDH + s0s * 8] = vr0;
    *(uint4*)&KV[2][r1s * STRDH + s1s * 8] = vr1;
    __syncthreads();

    const int NT = S_ / 64;
    for (int kt = 0; kt < NT; kt++) {
        const int c = kt & 1;
        if (kt + 1 < NT) {
            const int k0n = (kt + 1) * 64;
            kr0 = *(const uint4*)&kb[(k0n + r0s) * D_ + s0s * 8];
            kr1 = *(const uint4*)&kb[(k0n + r1s) * D_ + s1s * 8];
            vr0 = *(const uint4*)&vb[(k0n + r0s) * D_ + s0s * 8];
            vr1 = *(const uint4*)&vb[(k0n + r1s) * D_ + s1s * 8];
        }

        float s[8][4] = {};
        #pragma unroll
        for (int kk = 0; kk < 4; kk++) {
            #pragma unroll
            for (int ntp = 0; ntp < 4; ntp++) {
                u32 b[4];
                ldsm4(b, ksb[c] + (u32)((ntp * 16 * STRDH + kk * 16) * 2));
                mma_f16(s[2 * ntp],     qf[kk], b[0], b[1]);
                mma_f16(s[2 * ntp + 1], qf[kk], b[2], b[3]);
            }
        }

        u32 pa[8][2];
        #pragma unroll
        for (int nt = 0; nt < 8; nt++) {
            pa[nt][0] = ex2_h2(s[nt][0] - SM_MAX, s[nt][1] - SM_MAX);
            pa[nt][1] = ex2_h2(s[nt][2] - SM_MAX, s[nt][3] - SM_MAX);
        }

        #pragma unroll
        for (int kk = 0; kk < 4; kk++) {
            u32 a[4] = { pa[2 * kk][0], pa[2 * kk][1],
                         pa[2 * kk + 1][0], pa[2 * kk + 1][1] };
            mma_f16(lacc, a, ONES_H2, ONES_H2);
            #pragma unroll
            for (int ntp = 0; ntp < 4; ntp++) {
                u32 b[4];
                ldsm4t(b, vsb[c] + (u32)((kk * 16 * STRDH + ntp * 16) * 2));
                mma_f16(o[2 * ntp],     a, b[0], b[1]);
                mma_f16(o[2 * ntp + 1], a, b[2], b[3]);
            }
        }

        if (kt + 1 < NT) {
            const int nb = 1 - c;
            *(uint4*)&KV[nb][r0s * STRDH + s0s * 8] = kr0;
            *(uint4*)&KV[nb][r1s * STRDH + s1s * 8] = kr1;
            *(uint4*)&KV[2 + nb][r0s * STRDH + s0s * 8] = vr0;
            *(uint4*)&KV[2 + nb][r1s * STRDH + s1s * 8] = vr1;
        }
        __syncthreads();
    }

    // =======================================================================
    // FUSED EPILOGUE (v3): ctxg pack -> 1 sync -> 32x {LDG.64 + ldsm + mma}.
    // Warp w computes D[16, cols 8w..8w+7] over all K=512. No staging/atomics.
    // =======================================================================
    __half* ctxg = (__half*)&KV[0][0];          // 16 * EROW halves (18688 B)

    // ---- O /= l, pack into ctx-global layout: ctxg[r][j*72 + d], j = qr ----
    float inv0 = 1.f / lacc[0], inv1 = 1.f / lacc[2];
    #pragma unroll
    for (int nt = 0; nt < 8; nt++) {
        int coff = qr * 72 + nt * 8 + 2 * qc;
        *(u32*)&ctxg[(2 * warp    ) * EROW + coff] = pack_h2(o[nt][0] * inv0, o[nt][1] * inv0);
        *(u32*)&ctxg[(2 * warp + 1) * EROW + coff] = pack_h2(o[nt][2] * inv1, o[nt][3] * inv1);
    }
    __syncthreads();

    const u32 actx = s2u(ctxg) +
        (u32)((((lane & 15) * EROW) + ((lane >> 4) * 8)) * 2);
    const uint2* wop = g_wop + warp * 1024 + lane;   // (warp*32 + kk)*32 + lane

    float ec[4] = {};
    #pragma unroll
    for (int kk = 0; kk < 32; kk++) {
        uint2 bfr = wop[kk * 32];
        u32 a[4];
        int aoff = (kk >> 2) * 72 + (kk & 3) * 16;   // chunk j = kk>>2, d = (kk&3)*16
        ldsm4(a, actx + (u32)(aoff * 2));
        mma_f16(ec, a, bfr.x, bfr.y);
    }

    *(float2*)&sacc[qr    ][warp * 8 + 2 * qc] = make_float2(ec[0], ec[1]);
    *(float2*)&sacc[qr + 8][warp * 8 + 2 * qc] = make_float2(ec[2], ec[3]);
    __syncthreads();

    // ---- + bias + residual, LayerNorm(64), write out. 16 threads / row ----
    {
        const int r = tid >> 4, t16 = tid & 15;
        const int Rg = gh * 256 + blockIdx.x * 16 + r;   // global row
        const int col = t16 * 4;
        float4 xa = *(const float4*)&x[Rg * D_ + col];
        float4 ba = *(const float4*)&bo[col];
        float y0 = sacc[r][col    ] + ba.x + xa.x;
        float y1 = sacc[r][col + 1] + ba.y + xa.y;
        float y2 = sacc[r][col + 2] + ba.z + xa.z;
        float y3 = sacc[r][col + 3] + ba.w + xa.w;
        float sm = y0 + y1 + y2 + y3;
        float sq = y0 * y0 + y1 * y1 + y2 * y2 + y3 * y3;
        #pragma unroll
        for (int off = 8; off; off >>= 1) {
            sm += __shfl_xor_sync(0xffffffffu, sm, off, 16);
            sq += __shfl_xor_sync(0xffffffffu, sq, off, 16);
        }
        float mu  = sm * (1.f / 64.f);
        float inv = rsqrtf(sq * (1.f / 64.f) - mu * mu + 1e-5f);
        float4 gm = *(const float4*)&gamma[col];
        float4 be = *(const float4*)&beta[col];
        float4 ov;
        ov.x = (y0 - mu) * inv * gm.x + be.x;
        ov.y = (y1 - mu) * inv * gm.y + be.y;
        ov.z = (y2 - mu) * inv * gm.z + be.z;
        ov.w = (y3 - mu) * inv * gm.w + be.w;
        *(float4*)&out[Rg * D_ + col] = ov;
    }
}

// ---------------------------------------------------------------------------
extern "C" void kernel_launch(void* const* d_in, const int* in_sizes, int n_in,
                              void* d_out, int out_size)
{
    const float* x     = (const float*)d_in[0];
    const float* Wq    = (const float*)d_in[1];
    const float* bq    = (const float*)d_in[2];
    const float* Wk    = (const float*)d_in[3];
    const float* bk    = (const float*)d_in[4];
    const float* Wv    = (const float*)d_in[5];
    const float* bv    = (const float*)d_in[6];
    const float* Wo    = (const float*)d_in[7];
    const float* bo    = (const float*)d_in[8];
    const float* gamma = (const float*)d_in[9];
    const float* beta  = (const float*)d_in[10];
    float* out = (float*)d_out;

    wo_prep<<<32, 256>>>(Wo);

    dim3 g1(BS_ / 128, HD_ / 128, 3);
    qkv_tc_kernel<<<g1, 256>>>(x, Wq, bq, Wk, bk, Wv, bv);

    dim3 g2(S_ / 128, GH_);
    attn_tc_kernel<<<g2, 256>>>(x, bo, gamma, beta, out);
}